// round 13
// baseline (speedup 1.0000x reference)
#include <cuda_runtime.h>
#include <cstdint>

// ---------------------------------------------------------------------------
// Round 12: R10 ST dedup + liveness gating on the combo precompute.
//   R10's regression was st_precompute doing all 960 combos (668 MB L2,
//   ~79us). Only ~127 combos are live for 8192 points; a 3us mark kernel
//   gates the precompute -> ~10us.
// ---------------------------------------------------------------------------

#define MPTS   32
#define TPB    256
#define KC     128
#define KPAD   9600          // spatial K only (9520 padded to 75*128)
#define NCH    (KPAD / KC)   // 75
#define SA     132           // A smem row stride (u32)
#define RS     72            // reduce buffer row stride (floats)
#define NK8    (KPAD / 8)    // 1200
#define NB     28            // spatial base-table entries per point
#define NCOMBO 960
#define NPTS   8192

__device__ uint4 g_Wf4[NK8 * 4 * 32];  // [(K8*4 + nt2)*32 + lane]
__device__ float g_Hst[NCOMBO * 64];   // per-combo ST partial h_pre
__device__ float g_SSst[NCOMBO];       // per-combo ST partial sumsq
__device__ int   g_live[NCOMBO];       // combo liveness flags

__constant__ int c_OFF7[7][3] = {
    {0,0,0},{1,0,0},{-1,0,0},{0,1,0},{0,-1,0},{0,0,1},{0,0,-1}};
__constant__ int c_S14[14][3] = {
    {1,0,0},{-1,0,0},{0,1,0},{0,-1,0},{0,0,1},{0,0,-1},
    {1,1,1},{-1,-1,-1},{1,-1,-1},{-1,1,1},{1,1,-1},{-1,-1,1},{1,-1,1},{-1,1,-1}};
__constant__ int c_CORNER[8][3] = {
    {1,1,1},{-1,-1,-1},{1,-1,-1},{-1,1,1},{1,1,-1},{-1,-1,1},{1,-1,1},{-1,1,-1}};
__constant__ int c_ETEMP[11] = {-64,-8,-4,-2,-1,0,1,2,4,8,64};

__device__ __forceinline__ uint32_t f2tf32(float x) {
    uint32_t u;
    asm("cvt.rna.tf32.f32 %0, %1;" : "=r"(u) : "f"(x));
    return u;
}

__device__ __forceinline__ uint32_t s2u(const void* p) {
    uint32_t a;
    asm("{ .reg .u64 t; cvta.to.shared.u64 t, %1; cvt.u32.u64 %0, t; }"
        : "=r"(a) : "l"(p));
    return a;
}

__device__ __forceinline__ void mma8(float* c,
                                     uint32_t a0, uint32_t a1, uint32_t a2, uint32_t a3,
                                     uint32_t b0, uint32_t b1) {
    asm("mma.sync.aligned.m16n8k8.row.col.f32.tf32.tf32.f32 "
        "{%0,%1,%2,%3}, {%4,%5,%6,%7}, {%8,%9}, {%0,%1,%2,%3};"
        : "+f"(c[0]), "+f"(c[1]), "+f"(c[2]), "+f"(c[3])
        : "r"(a0), "r"(a1), "r"(a2), "r"(a3), "r"(b0), "r"(b1));
}

// ---------------------------------------------------------------------------
__global__ void __launch_bounds__(256)
wf_precompute_kernel(const float* __restrict__ w_down,
                     const float* __restrict__ rms_scale)
{
    int T = blockIdx.x * 256 + threadIdx.x;
    if (T >= NK8 * 4 * 32) return;
    int lane = T & 31;
    int nt2  = (T >> 5) & 3;
    int K8   = T >> 7;
    int ne = nt2 * 16 + (lane >> 2);
    int no = ne + 8;
    int k0 = K8 * 8 + (lane & 3);
    int k1 = k0 + 4;
    uint4 u;
    u.x = (k0 < 9520) ? f2tf32(w_down[k0 * 64 + ne] * rms_scale[k0]) : 0u;
    u.y = (k1 < 9520) ? f2tf32(w_down[k1 * 64 + ne] * rms_scale[k1]) : 0u;
    u.z = (k0 < 9520) ? f2tf32(w_down[k0 * 64 + no] * rms_scale[k0]) : 0u;
    u.w = (k1 < 9520) ? f2tf32(w_down[k1 * 64 + no] * rms_scale[k1]) : 0u;
    g_Wf4[T] = u;
}

// ---------------------------------------------------------------------------
// Mark live combos: single block, zero flags then set from t. Deterministic.
__global__ void __launch_bounds__(960)
mark_live_kernel(const float* __restrict__ d_t)
{
    int tid = threadIdx.x;
    if (tid < NCOMBO) g_live[tid] = 0;
    __syncthreads();
    for (int i = tid; i < NPTS; i += 960) {
        float tv = d_t[i];
        int key = ((int)(tv * 15.0f)) * 64 + (int)(tv * 63.0f);
        g_live[key] = 1;
    }
}

// ---------------------------------------------------------------------------
// ST combo precompute (gated): one block per (tb,tv) combo.
// A = tf32-truncate(relu f) (RZ), B = tf32-rna(w*s), fp32 accumulate.
__global__ void __launch_bounds__(256)
st_precompute_kernel(const float* __restrict__ S1t,
                     const float* __restrict__ S2t,
                     const float* __restrict__ TF,
                     const float* __restrict__ w_down,
                     const float* __restrict__ rms_scale)
{
    __shared__ float red[256];
    __shared__ float ssred[4];
    int c = blockIdx.x;
    if (!g_live[c]) return;
    int tb = c >> 6, tv = c & 63;
    int n  = threadIdx.x & 63;
    int sl = threadIdx.x >> 6;
    float acc = 0.f, ss = 0.f;

    // 144 offset-groups: [0,28) st1 F=64 | [28,56) st2 F=8 | [56,144) tf3 F=8
    for (int g = sl; g < 144; g += 4) {
        const float* fp; int kbase, F;
        if (g < 28) {
            int si = g >> 1; int tt = (g & 1) ? -1 : 1;
            int a  = (tb + c_S14[si][0] + 16) & 15;
            int b  = (tb + c_S14[si][1] + 16) & 15;
            int cc = (tb + c_S14[si][2] + 16) & 15;
            int dd = (tv + tt + 64) & 63;
            fp = S1t + (((((((a << 4) | b) << 4) | cc) << 6) | dd) << 6);
            kbase = 9520 + g * 64; F = 64;
        } else if (g < 56) {
            int gg = g - 28; int si = gg >> 1; int tt = (gg & 1) ? -1 : 1;
            int a  = (tb + c_S14[si][0] + 64) & 63;
            int b  = (tb + c_S14[si][1] + 64) & 63;
            int cc = (tb + c_S14[si][2] + 64) & 63;
            int dd = (tv + tt + 64) & 63;
            fp = S2t + (((((((a << 6) | b) << 6) | cc) << 6) | dd) << 3);
            kbase = 11312 + gg * 8; F = 8;
        } else {
            int gg = g - 56; int ci = gg / 11, ti = gg - ci * 11;
            int a  = (tb + c_CORNER[ci][0] + 4) & 3;
            int b  = (tb + c_CORNER[ci][1] + 4) & 3;
            int cc = (tb + c_CORNER[ci][2] + 4) & 3;
            int dd = (tv + c_ETEMP[ti] + 65536) & 65535;
            fp = TF + (((((((a << 2) | b) << 2) | cc) << 16) | dd) << 3);
            kbase = 11536 + gg * 8; F = 8;
        }
        for (int f = 0; f < F; f++) {
            float fr = fmaxf(fp[f], 0.f);
            ss += fr * fr;
            float av = __uint_as_float(__float_as_uint(fr) & 0xFFFFE000u);
            int k = kbase + f;
            float wv = __uint_as_float(f2tf32(w_down[k * 64 + n] * rms_scale[k]));
            acc += av * wv;
        }
    }
    red[threadIdx.x] = acc;
    if (n == 0) ssred[sl] = ss;
    __syncthreads();
    if (sl == 0) {
        g_Hst[c * 64 + n] = red[n] + red[64 + n] + red[128 + n] + red[192 + n];
        if (n == 0) g_SSst[c] = ssred[0] + ssred[1] + ssred[2] + ssred[3];
    }
}

// ---------------------------------------------------------------------------
// Gather 4 consecutive spatial features via precomputed per-point base table.
__device__ __forceinline__ float4 gather4b(
    int k, const int* __restrict__ bp,
    const float* __restrict__ T0, const float* __restrict__ T1,
    const float* __restrict__ T2, const float* __restrict__ T3)
{
    if (k < 9520) {
        const float* tab; int r, flog, bi;
        if (k < 112)       { tab = T0; r = k;        flog = 4;  bi = 0;  }
        else if (k < 560)  { tab = T1; r = k - 112;  flog = 6;  bi = 7;  }
        else if (k < 2352) { tab = T2; r = k - 560;  flog = 8;  bi = 14; }
        else               { tab = T3; r = k - 2352; flog = 10; bi = 21; }
        int o = r >> flog;
        int f = r & ((1 << flog) - 1);
        return *reinterpret_cast<const float4*>(tab + bp[bi + o] + f);
    }
    return make_float4(0.f, 0.f, 0.f, 0.f);   // pad [9520,9600)
}

// ---------------------------------------------------------------------------
__global__ void __launch_bounds__(TPB, 2)
stlt_fused_kernel(
    const float* __restrict__ d_pos, const float* __restrict__ d_dir,
    const float* __restrict__ d_t,
    const float* __restrict__ T0, const float* __restrict__ T1,
    const float* __restrict__ T2, const float* __restrict__ T3,
    const float* __restrict__ w_final, const float* __restrict__ b_final,
    float* __restrict__ d_out)
{
    __shared__ alignas(16) uint32_t As[2 * MPTS * SA];   // double-buffered A
    __shared__ alignas(16) float    Rbuf[MPTS * RS];
    __shared__ int      bases[MPTS * NB];
    __shared__ int      pidx[MPTS][12];
    __shared__ int      key_s[MPTS];
    __shared__ float    sumsq_s[MPTS];

    const int tid  = threadIdx.x;
    const int lane = tid & 31;
    const int warp = tid >> 5;
    const int kq   = warp >> 1;     // k-quarter 0..3
    const int nh   = warp & 1;      // n-half 0..1 (cols [nh*32, +32))
    const int p0   = blockIdx.x * MPTS;

    if (tid < MPTS) {
        int gp = p0 + tid;
        float px = d_pos[gp * 3 + 0];
        float py = d_pos[gp * 3 + 1];
        float pz = d_pos[gp * 3 + 2];
        pidx[tid][0]  = (int)(px * 127.0f);
        pidx[tid][1]  = (int)(py * 127.0f);
        pidx[tid][2]  = (int)(pz * 127.0f);
        pidx[tid][3]  = (int)(px * 63.0f);
        pidx[tid][4]  = (int)(py * 63.0f);
        pidx[tid][5]  = (int)(pz * 63.0f);
        pidx[tid][6]  = (int)(px * 31.0f);
        pidx[tid][7]  = (int)(py * 31.0f);
        pidx[tid][8]  = (int)(pz * 31.0f);
        pidx[tid][9]  = (int)(px * 15.0f);
        pidx[tid][10] = (int)(py * 15.0f);
        pidx[tid][11] = (int)(pz * 15.0f);
        float tv = d_t[gp];
        key_s[tid] = ((int)(tv * 15.0f)) * 64 + (int)(tv * 63.0f);
    }
    __syncthreads();

    // ---- fill per-point spatial base-address table -------------------------
    for (int e = tid; e < MPTS * NB; e += TPB) {
        int p = e / NB;
        int j = e - p * NB;
        int tau  = j / 7;
        int o    = j - tau * 7;
        int dlog = 7 - tau;
        int flog = 4 + 2 * tau;
        int d = 1 << dlog, m = d - 1;
        int cx = (pidx[p][tau * 3 + 0] + c_OFF7[o][0] + d) & m;
        int cy = (pidx[p][tau * 3 + 1] + c_OFF7[o][1] + d) & m;
        int cz = (pidx[p][tau * 3 + 2] + c_OFF7[o][2] + d) & m;
        bases[e] = ((((cx << dlog) | cy) << dlog) | cz) << flog;
    }
    __syncthreads();

    float acc[2][4][4];
#pragma unroll
    for (int m = 0; m < 2; m++)
#pragma unroll
        for (int i = 0; i < 4; i++)
#pragma unroll
            for (int j = 0; j < 4; j++) acc[m][i][j] = 0.f;
    float ss[4] = {0.f, 0.f, 0.f, 0.f};

    const int lm_row = ((lane >> 3) & 1) * 8 + (lane & 7);
    const int lm_kof = (lane >> 4) * 4;

    // ---- prologue: gather chunk 0 into regs (4 float4 per thread) ---------
    float4 v[4];
#pragma unroll
    for (int j = 0; j < 4; j++) {
        int i  = tid + j * TPB;
        int p  = i >> 5;
        int k4 = (i & 31) << 2;
        v[j] = gather4b(k4, bases + p * NB, T0, T1, T2, T3);
    }

    for (int ch = 0; ch < NCH; ch++) {
        uint32_t* buf = As + (ch & 1) * (MPTS * SA);
        const int kb  = ch * KC;

        // ---- STS: relu + per-thread sumsq + store raw fp32 bits ----------
#pragma unroll
        for (int j = 0; j < 4; j++) {
            float4 w = v[j];
            w.x = fmaxf(w.x, 0.f); w.y = fmaxf(w.y, 0.f);
            w.z = fmaxf(w.z, 0.f); w.w = fmaxf(w.w, 0.f);
            ss[j] += w.x * w.x + w.y * w.y + w.z * w.z + w.w * w.w;
            int i = tid + j * TPB;
            *reinterpret_cast<float4*>(&buf[(i >> 5) * SA + ((i & 31) << 2)]) = w;
        }
        __syncthreads();

        // ---- prefetch next chunk (overlaps mma) ---------------------------
        if (ch + 1 < NCH) {
#pragma unroll
            for (int j = 0; j < 4; j++) {
                int i  = tid + j * TPB;
                int p  = i >> 5;
                int k4 = (i & 31) << 2;
                v[j] = gather4b(kb + KC + k4, bases + p * NB, T0, T1, T2, T3);
            }
        }

        // ---- mma: warp covers k8 in [kq*4, +4), n [nh*32, +32), m all 32 --
#pragma unroll
        for (int g = 0; g < 4; g++) {
            int K8l = kq * 4 + g;
            int kk  = K8l * 8;
            const uint4* Wk = g_Wf4 + ((size_t)(ch * 16 + K8l) << 7) + lane;
            uint4 bq0 = Wk[(2 * nh) * 32];
            uint4 bq1 = Wk[(2 * nh + 1) * 32];
#pragma unroll
            for (int mt = 0; mt < 2; mt++) {
                uint32_t a0, a1, a2, a3;
                uint32_t addr = s2u(&buf[(mt * 16 + lm_row) * SA + kk + lm_kof]);
                asm volatile("ldmatrix.sync.aligned.m8n8.x4.shared.b16 {%0,%1,%2,%3}, [%4];"
                             : "=r"(a0), "=r"(a1), "=r"(a2), "=r"(a3) : "r"(addr));
                mma8(acc[mt][0], a0, a1, a2, a3, bq0.x, bq0.y);
                mma8(acc[mt][1], a0, a1, a2, a3, bq0.z, bq0.w);
                mma8(acc[mt][2], a0, a1, a2, a3, bq1.x, bq1.y);
                mma8(acc[mt][3], a0, a1, a2, a3, bq1.z, bq1.w);
            }
        }
    }

    // ---- sumsq: warp reduce + add ST combo part, single writer ------------
#pragma unroll
    for (int s = 16; s >= 1; s >>= 1) {
#pragma unroll
        for (int j = 0; j < 4; j++)
            ss[j] += __shfl_xor_sync(0xffffffffu, ss[j], s);
    }
    if (lane == 0) {
#pragma unroll
        for (int j = 0; j < 4; j++) {
            int p = warp + 8 * j;
            sumsq_s[p] = ss[j] + g_SSst[key_s[p]];
        }
    }

    // ---- cross-k acc reduction (serialized by kq; both nh in parallel) ----
    {
        int row = lane >> 2;
        int cb  = nh * 32 + (lane & 3) * 2;
        if (kq == 3) {
#pragma unroll
            for (int mt = 0; mt < 2; mt++)
#pragma unroll
            for (int nt = 0; nt < 4; nt++) {
                int col = cb + nt * 8;
                int r0 = mt * 16 + row;
                Rbuf[r0 * RS + col]           = acc[mt][nt][0];
                Rbuf[r0 * RS + col + 1]       = acc[mt][nt][1];
                Rbuf[(r0 + 8) * RS + col]     = acc[mt][nt][2];
                Rbuf[(r0 + 8) * RS + col + 1] = acc[mt][nt][3];
            }
        }
        __syncthreads();
        if (kq == 2) {
#pragma unroll
            for (int mt = 0; mt < 2; mt++)
#pragma unroll
            for (int nt = 0; nt < 4; nt++) {
                int col = cb + nt * 8;
                int r0 = mt * 16 + row;
                Rbuf[r0 * RS + col]           += acc[mt][nt][0];
                Rbuf[r0 * RS + col + 1]       += acc[mt][nt][1];
                Rbuf[(r0 + 8) * RS + col]     += acc[mt][nt][2];
                Rbuf[(r0 + 8) * RS + col + 1] += acc[mt][nt][3];
            }
        }
        __syncthreads();
        if (kq == 1) {
#pragma unroll
            for (int mt = 0; mt < 2; mt++)
#pragma unroll
            for (int nt = 0; nt < 4; nt++) {
                int col = cb + nt * 8;
                int r0 = mt * 16 + row;
                Rbuf[r0 * RS + col]           += acc[mt][nt][0];
                Rbuf[r0 * RS + col + 1]       += acc[mt][nt][1];
                Rbuf[(r0 + 8) * RS + col]     += acc[mt][nt][2];
                Rbuf[(r0 + 8) * RS + col + 1] += acc[mt][nt][3];
            }
        }
        __syncthreads();
        if (kq == 0) {
#pragma unroll
            for (int mt = 0; mt < 2; mt++) {
                int r0 = mt * 16 + row;
                int r1 = r0 + 8;
                const float* H0 = g_Hst + key_s[r0] * 64;
                const float* H1 = g_Hst + key_s[r1] * 64;
                float inv0 = 1.0f / (sqrtf(sumsq_s[r0] * (1.0f / 12240.0f)) + 1e-8f);
                float inv1 = 1.0f / (sqrtf(sumsq_s[r1] * (1.0f / 12240.0f)) + 1e-8f);
#pragma unroll
                for (int nt = 0; nt < 4; nt++) {
                    int col = cb + nt * 8;
                    Rbuf[r0 * RS + col]     = fmaxf((acc[mt][nt][0] + Rbuf[r0 * RS + col]     + H0[col])     * inv0, 0.f);
                    Rbuf[r0 * RS + col + 1] = fmaxf((acc[mt][nt][1] + Rbuf[r0 * RS + col + 1] + H0[col + 1]) * inv0, 0.f);
                    Rbuf[r1 * RS + col]     = fmaxf((acc[mt][nt][2] + Rbuf[r1 * RS + col]     + H1[col])     * inv1, 0.f);
                    Rbuf[r1 * RS + col + 1] = fmaxf((acc[mt][nt][3] + Rbuf[r1 * RS + col + 1] + H1[col + 1]) * inv1, 0.f);
                }
            }
        }
    }
    __syncthreads();

    // ---- final tiny layer + sigmoid ---------------------------------------
    if (tid < MPTS) {
        int gp = p0 + tid;
        float o0 = b_final[0], o1 = b_final[1], o2 = b_final[2], o3 = b_final[3];
#pragma unroll 8
        for (int i = 0; i < 64; i++) {
            float h = Rbuf[tid * RS + i];
            float4 wf = *reinterpret_cast<const float4*>(w_final + i * 4);
            o0 += h * wf.x; o1 += h * wf.y; o2 += h * wf.z; o3 += h * wf.w;
        }
#pragma unroll
        for (int c = 0; c < 3; c++) {
            float dv = d_dir[gp * 3 + c];
            float4 wf = *reinterpret_cast<const float4*>(w_final + (64 + c) * 4);
            o0 += dv * wf.x; o1 += dv * wf.y; o2 += dv * wf.z; o3 += dv * wf.w;
        }
        {
            float tv = d_t[gp];
            float4 wf = *reinterpret_cast<const float4*>(w_final + 67 * 4);
            o0 += tv * wf.x; o1 += tv * wf.y; o2 += tv * wf.z; o3 += tv * wf.w;
        }
        d_out[gp * 4 + 0] = 1.0f / (1.0f + expf(-o0));
        d_out[gp * 4 + 1] = 1.0f / (1.0f + expf(-o1));
        d_out[gp * 4 + 2] = 1.0f / (1.0f + expf(-o2));
        d_out[gp * 4 + 3] = 1.0f / (1.0f + expf(-o3));
    }
}

extern "C" void kernel_launch(void* const* d_in, const int* in_sizes, int n_in,
                              void* d_out, int out_size) {
    const float* pos       = (const float*)d_in[0];
    const float* dirv      = (const float*)d_in[1];
    const float* t         = (const float*)d_in[2];
    const float* table0    = (const float*)d_in[3];
    const float* table1    = (const float*)d_in[4];
    const float* table2    = (const float*)d_in[5];
    const float* table3    = (const float*)d_in[6];
    const float* st1       = (const float*)d_in[7];
    const float* st2       = (const float*)d_in[8];
    const float* tf3       = (const float*)d_in[9];
    const float* rms_scale = (const float*)d_in[10];
    const float* w_down    = (const float*)d_in[11];
    const float* w_final   = (const float*)d_in[12];
    const float* b_final   = (const float*)d_in[13];
    float* out = (float*)d_out;

    wf_precompute_kernel<<<(NK8 * 4 * 32 + 255) / 256, 256>>>(w_down, rms_scale);
    mark_live_kernel<<<1, 960>>>(t);
    st_precompute_kernel<<<NCOMBO, 256>>>(st1, st2, tf3, w_down, rms_scale);
    stlt_fused_kernel<<<8192 / MPTS, TPB>>>(
        pos, dirv, t, table0, table1, table2, table3,
        w_final, b_final, out);
}

// round 14
// speedup vs baseline: 1.5004x; 1.5004x over previous
#include <cuda_runtime.h>
#include <cstdint>

// ---------------------------------------------------------------------------
// Round 13: helper-kernel rescue for the ST dedup.
//   Main kernel unchanged (114.7us proven). st_precompute rebuilt:
//   smem-staged features + precomputed g_Wst + unroll-8 MLP dot product;
//   ss reduced once per block. g_Wst fill + g_live zero folded into wf.
// ---------------------------------------------------------------------------

#define MPTS   32
#define TPB    256
#define KC     128
#define KPAD   9600          // spatial K only (9520 padded to 75*128)
#define NCH    (KPAD / KC)   // 75
#define SA     132           // A smem row stride (u32)
#define RS     72            // reduce buffer row stride (floats)
#define NK8    (KPAD / 8)    // 1200
#define NB     28            // spatial base-table entries per point
#define NCOMBO 960
#define NPTS   8192
#define STK    2720          // ST k-range size
#define WF4_N  (NK8 * 4 * 32)      // 153600
#define WST_N  (STK * 16)          // 43520 float4 slots

__device__ uint4 g_Wf4[NK8 * 4 * 32];  // spatial B fragments
__device__ float g_Wst[STK * 64];      // ST B values tf32-rna, [k-9520][n]
__device__ float g_Hst[NCOMBO * 64];   // per-combo ST partial h_pre
__device__ float g_SSst[NCOMBO];       // per-combo ST partial sumsq
__device__ int   g_live[NCOMBO];       // combo liveness flags

__constant__ int c_OFF7[7][3] = {
    {0,0,0},{1,0,0},{-1,0,0},{0,1,0},{0,-1,0},{0,0,1},{0,0,-1}};
__constant__ int c_S14[14][3] = {
    {1,0,0},{-1,0,0},{0,1,0},{0,-1,0},{0,0,1},{0,0,-1},
    {1,1,1},{-1,-1,-1},{1,-1,-1},{-1,1,1},{1,1,-1},{-1,-1,1},{1,-1,1},{-1,1,-1}};
__constant__ int c_CORNER[8][3] = {
    {1,1,1},{-1,-1,-1},{1,-1,-1},{-1,1,1},{1,1,-1},{-1,-1,1},{1,-1,1},{-1,1,-1}};
__constant__ int c_ETEMP[11] = {-64,-8,-4,-2,-1,0,1,2,4,8,64};

__device__ __forceinline__ uint32_t f2tf32(float x) {
    uint32_t u;
    asm("cvt.rna.tf32.f32 %0, %1;" : "=r"(u) : "f"(x));
    return u;
}

__device__ __forceinline__ uint32_t s2u(const void* p) {
    uint32_t a;
    asm("{ .reg .u64 t; cvta.to.shared.u64 t, %1; cvt.u32.u64 %0, t; }"
        : "=r"(a) : "l"(p));
    return a;
}

__device__ __forceinline__ void mma8(float* c,
                                     uint32_t a0, uint32_t a1, uint32_t a2, uint32_t a3,
                                     uint32_t b0, uint32_t b1) {
    asm("mma.sync.aligned.m16n8k8.row.col.f32.tf32.tf32.f32 "
        "{%0,%1,%2,%3}, {%4,%5,%6,%7}, {%8,%9}, {%0,%1,%2,%3};"
        : "+f"(c[0]), "+f"(c[1]), "+f"(c[2]), "+f"(c[3])
        : "r"(a0), "r"(a1), "r"(a2), "r"(a3), "r"(b0), "r"(b1));
}

// ---------------------------------------------------------------------------
// Combined precompute: spatial B fragments, ST B values, g_live zero.
__global__ void __launch_bounds__(256)
wf_precompute_kernel(const float* __restrict__ w_down,
                     const float* __restrict__ rms_scale)
{
    int T = blockIdx.x * 256 + threadIdx.x;
    if (T < WF4_N) {
        int lane = T & 31;
        int nt2  = (T >> 5) & 3;
        int K8   = T >> 7;
        int ne = nt2 * 16 + (lane >> 2);
        int no = ne + 8;
        int k0 = K8 * 8 + (lane & 3);
        int k1 = k0 + 4;
        uint4 u;
        u.x = (k0 < 9520) ? f2tf32(w_down[k0 * 64 + ne] * rms_scale[k0]) : 0u;
        u.y = (k1 < 9520) ? f2tf32(w_down[k1 * 64 + ne] * rms_scale[k1]) : 0u;
        u.z = (k0 < 9520) ? f2tf32(w_down[k0 * 64 + no] * rms_scale[k0]) : 0u;
        u.w = (k1 < 9520) ? f2tf32(w_down[k1 * 64 + no] * rms_scale[k1]) : 0u;
        g_Wf4[T] = u;
    } else if (T < WF4_N + WST_N) {
        int idx = T - WF4_N;
        int kk  = idx >> 4;            // 0..2719
        int n4  = (idx & 15) << 2;
        int k   = 9520 + kk;
        float s = rms_scale[k];
        float4 w = *reinterpret_cast<const float4*>(w_down + k * 64 + n4);
        float4 o;
        o.x = __uint_as_float(f2tf32(w.x * s));
        o.y = __uint_as_float(f2tf32(w.y * s));
        o.z = __uint_as_float(f2tf32(w.z * s));
        o.w = __uint_as_float(f2tf32(w.w * s));
        *reinterpret_cast<float4*>(g_Wst + kk * 64 + n4) = o;
    } else if (T < WF4_N + WST_N + NCOMBO) {
        g_live[T - WF4_N - WST_N] = 0;
    }
}

// ---------------------------------------------------------------------------
// Mark live combos (multi-block; racy =1 stores are benign + deterministic).
__global__ void __launch_bounds__(256)
mark_live_kernel(const float* __restrict__ d_t)
{
    int i = blockIdx.x * 256 + threadIdx.x;
    if (i < NPTS) {
        float tv = d_t[i];
        int key = ((int)(tv * 15.0f)) * 64 + (int)(tv * 63.0f);
        g_live[key] = 1;
    }
}

// ---------------------------------------------------------------------------
// ST combo precompute (gated), latency-optimized.
// Phase 1: stage 2720 relu'd+masked features in smem (ss reduced once).
// Phase 2: unroll-8 dot vs g_Wst (LDS broadcast + coalesced LDG).
__global__ void __launch_bounds__(256)
st_precompute_kernel(const float* __restrict__ S1t,
                     const float* __restrict__ S2t,
                     const float* __restrict__ TF)
{
    __shared__ int   gbase[144];
    __shared__ float fst[STK];
    __shared__ float red[256];

    int c = blockIdx.x;
    if (!g_live[c]) return;
    int tb = c >> 6, tvv = c & 63;
    int tid = threadIdx.x;

    // group base offsets for this combo
    if (tid < 144) {
        int g = tid, b;
        if (g < 28) {
            int si = g >> 1; int tt = (g & 1) ? -1 : 1;
            int a  = (tb + c_S14[si][0] + 16) & 15;
            int bb = (tb + c_S14[si][1] + 16) & 15;
            int cc = (tb + c_S14[si][2] + 16) & 15;
            int dd = (tvv + tt + 64) & 63;
            b = (((((((a << 4) | bb) << 4) | cc) << 6) | dd) << 6);
        } else if (g < 56) {
            int gg = g - 28; int si = gg >> 1; int tt = (gg & 1) ? -1 : 1;
            int a  = (tb + c_S14[si][0] + 64) & 63;
            int bb = (tb + c_S14[si][1] + 64) & 63;
            int cc = (tb + c_S14[si][2] + 64) & 63;
            int dd = (tvv + tt + 64) & 63;
            b = (((((((a << 6) | bb) << 6) | cc) << 6) | dd) << 3);
        } else {
            int gg = g - 56; int ci = gg / 11, ti = gg - ci * 11;
            int a  = (tb + c_CORNER[ci][0] + 4) & 3;
            int bb = (tb + c_CORNER[ci][1] + 4) & 3;
            int cc = (tb + c_CORNER[ci][2] + 4) & 3;
            int dd = (tvv + c_ETEMP[ti] + 65536) & 65535;
            b = (((((((a << 2) | bb) << 2) | cc) << 16) | dd) << 3);
        }
        gbase[g] = b;
    }
    __syncthreads();

    // Phase 1: load features (float4), relu, ss, store tf32-masked to smem.
    float ssp = 0.f;
    for (int e4 = tid; e4 < STK / 4; e4 += 256) {
        int r = e4 << 2;                   // k - 9520
        const float* fp;
        if (r < 1792)      fp = S1t + gbase[r >> 6] + (r & 63);
        else if (r < 2016) { int rr = r - 1792; fp = S2t + gbase[28 + (rr >> 3)] + (rr & 7); }
        else               { int rr = r - 2016; fp = TF  + gbase[56 + (rr >> 3)] + (rr & 7); }
        float4 v = *reinterpret_cast<const float4*>(fp);
        v.x = fmaxf(v.x, 0.f); v.y = fmaxf(v.y, 0.f);
        v.z = fmaxf(v.z, 0.f); v.w = fmaxf(v.w, 0.f);
        ssp += v.x * v.x + v.y * v.y + v.z * v.z + v.w * v.w;
        fst[r + 0] = __uint_as_float(__float_as_uint(v.x) & 0xFFFFE000u);
        fst[r + 1] = __uint_as_float(__float_as_uint(v.y) & 0xFFFFE000u);
        fst[r + 2] = __uint_as_float(__float_as_uint(v.z) & 0xFFFFE000u);
        fst[r + 3] = __uint_as_float(__float_as_uint(v.w) & 0xFFFFE000u);
    }
    red[tid] = ssp;
    __syncthreads();
    for (int s = 128; s > 0; s >>= 1) {
        if (tid < s) red[tid] += red[tid + s];
        __syncthreads();
    }
    float ssT = red[0];     // valid in all threads after the final sync
    __syncthreads();        // protect red before reuse

    // Phase 2: dot product. thread = (slice sl, col n); slice owns 680 k.
    int n  = tid & 63;
    int sl = tid >> 6;
    int k0 = sl * (STK / 4);
    float acc = 0.f;
#pragma unroll 8
    for (int j = 0; j < STK / 4; j++) {
        acc += fst[k0 + j] * g_Wst[(k0 + j) * 64 + n];
    }
    red[tid] = acc;
    __syncthreads();
    if (sl == 0) {
        g_Hst[c * 64 + n] = red[n] + red[64 + n] + red[128 + n] + red[192 + n];
        if (n == 0) g_SSst[c] = ssT;
    }
}

// ---------------------------------------------------------------------------
// Gather 4 consecutive spatial features via precomputed per-point base table.
__device__ __forceinline__ float4 gather4b(
    int k, const int* __restrict__ bp,
    const float* __restrict__ T0, const float* __restrict__ T1,
    const float* __restrict__ T2, const float* __restrict__ T3)
{
    if (k < 9520) {
        const float* tab; int r, flog, bi;
        if (k < 112)       { tab = T0; r = k;        flog = 4;  bi = 0;  }
        else if (k < 560)  { tab = T1; r = k - 112;  flog = 6;  bi = 7;  }
        else if (k < 2352) { tab = T2; r = k - 560;  flog = 8;  bi = 14; }
        else               { tab = T3; r = k - 2352; flog = 10; bi = 21; }
        int o = r >> flog;
        int f = r & ((1 << flog) - 1);
        return *reinterpret_cast<const float4*>(tab + bp[bi + o] + f);
    }
    return make_float4(0.f, 0.f, 0.f, 0.f);   // pad [9520,9600)
}

// ---------------------------------------------------------------------------
__global__ void __launch_bounds__(TPB, 2)
stlt_fused_kernel(
    const float* __restrict__ d_pos, const float* __restrict__ d_dir,
    const float* __restrict__ d_t,
    const float* __restrict__ T0, const float* __restrict__ T1,
    const float* __restrict__ T2, const float* __restrict__ T3,
    const float* __restrict__ w_final, const float* __restrict__ b_final,
    float* __restrict__ d_out)
{
    __shared__ alignas(16) uint32_t As[2 * MPTS * SA];   // double-buffered A
    __shared__ alignas(16) float    Rbuf[MPTS * RS];
    __shared__ int      bases[MPTS * NB];
    __shared__ int      pidx[MPTS][12];
    __shared__ int      key_s[MPTS];
    __shared__ float    sumsq_s[MPTS];

    const int tid  = threadIdx.x;
    const int lane = tid & 31;
    const int warp = tid >> 5;
    const int kq   = warp >> 1;     // k-quarter 0..3
    const int nh   = warp & 1;      // n-half 0..1 (cols [nh*32, +32))
    const int p0   = blockIdx.x * MPTS;

    if (tid < MPTS) {
        int gp = p0 + tid;
        float px = d_pos[gp * 3 + 0];
        float py = d_pos[gp * 3 + 1];
        float pz = d_pos[gp * 3 + 2];
        pidx[tid][0]  = (int)(px * 127.0f);
        pidx[tid][1]  = (int)(py * 127.0f);
        pidx[tid][2]  = (int)(pz * 127.0f);
        pidx[tid][3]  = (int)(px * 63.0f);
        pidx[tid][4]  = (int)(py * 63.0f);
        pidx[tid][5]  = (int)(pz * 63.0f);
        pidx[tid][6]  = (int)(px * 31.0f);
        pidx[tid][7]  = (int)(py * 31.0f);
        pidx[tid][8]  = (int)(pz * 31.0f);
        pidx[tid][9]  = (int)(px * 15.0f);
        pidx[tid][10] = (int)(py * 15.0f);
        pidx[tid][11] = (int)(pz * 15.0f);
        float tv = d_t[gp];
        key_s[tid] = ((int)(tv * 15.0f)) * 64 + (int)(tv * 63.0f);
    }
    __syncthreads();

    // ---- fill per-point spatial base-address table -------------------------
    for (int e = tid; e < MPTS * NB; e += TPB) {
        int p = e / NB;
        int j = e - p * NB;
        int tau  = j / 7;
        int o    = j - tau * 7;
        int dlog = 7 - tau;
        int flog = 4 + 2 * tau;
        int d = 1 << dlog, m = d - 1;
        int cx = (pidx[p][tau * 3 + 0] + c_OFF7[o][0] + d) & m;
        int cy = (pidx[p][tau * 3 + 1] + c_OFF7[o][1] + d) & m;
        int cz = (pidx[p][tau * 3 + 2] + c_OFF7[o][2] + d) & m;
        bases[e] = ((((cx << dlog) | cy) << dlog) | cz) << flog;
    }
    __syncthreads();

    float acc[2][4][4];
#pragma unroll
    for (int m = 0; m < 2; m++)
#pragma unroll
        for (int i = 0; i < 4; i++)
#pragma unroll
            for (int j = 0; j < 4; j++) acc[m][i][j] = 0.f;
    float ss[4] = {0.f, 0.f, 0.f, 0.f};

    const int lm_row = ((lane >> 3) & 1) * 8 + (lane & 7);
    const int lm_kof = (lane >> 4) * 4;

    // ---- prologue: gather chunk 0 into regs (4 float4 per thread) ---------
    float4 v[4];
#pragma unroll
    for (int j = 0; j < 4; j++) {
        int i  = tid + j * TPB;
        int p  = i >> 5;
        int k4 = (i & 31) << 2;
        v[j] = gather4b(k4, bases + p * NB, T0, T1, T2, T3);
    }

    for (int ch = 0; ch < NCH; ch++) {
        uint32_t* buf = As + (ch & 1) * (MPTS * SA);
        const int kb  = ch * KC;

        // ---- STS: relu + per-thread sumsq + store raw fp32 bits ----------
#pragma unroll
        for (int j = 0; j < 4; j++) {
            float4 w = v[j];
            w.x = fmaxf(w.x, 0.f); w.y = fmaxf(w.y, 0.f);
            w.z = fmaxf(w.z, 0.f); w.w = fmaxf(w.w, 0.f);
            ss[j] += w.x * w.x + w.y * w.y + w.z * w.z + w.w * w.w;
            int i = tid + j * TPB;
            *reinterpret_cast<float4*>(&buf[(i >> 5) * SA + ((i & 31) << 2)]) = w;
        }
        __syncthreads();

        // ---- prefetch next chunk (overlaps mma) ---------------------------
        if (ch + 1 < NCH) {
#pragma unroll
            for (int j = 0; j < 4; j++) {
                int i  = tid + j * TPB;
                int p  = i >> 5;
                int k4 = (i & 31) << 2;
                v[j] = gather4b(kb + KC + k4, bases + p * NB, T0, T1, T2, T3);
            }
        }

        // ---- mma: warp covers k8 in [kq*4, +4), n [nh*32, +32), m all 32 --
#pragma unroll
        for (int g = 0; g < 4; g++) {
            int K8l = kq * 4 + g;
            int kk  = K8l * 8;
            const uint4* Wk = g_Wf4 + ((size_t)(ch * 16 + K8l) << 7) + lane;
            uint4 bq0 = Wk[(2 * nh) * 32];
            uint4 bq1 = Wk[(2 * nh + 1) * 32];
#pragma unroll
            for (int mt = 0; mt < 2; mt++) {
                uint32_t a0, a1, a2, a3;
                uint32_t addr = s2u(&buf[(mt * 16 + lm_row) * SA + kk + lm_kof]);
                asm volatile("ldmatrix.sync.aligned.m8n8.x4.shared.b16 {%0,%1,%2,%3}, [%4];"
                             : "=r"(a0), "=r"(a1), "=r"(a2), "=r"(a3) : "r"(addr));
                mma8(acc[mt][0], a0, a1, a2, a3, bq0.x, bq0.y);
                mma8(acc[mt][1], a0, a1, a2, a3, bq0.z, bq0.w);
                mma8(acc[mt][2], a0, a1, a2, a3, bq1.x, bq1.y);
                mma8(acc[mt][3], a0, a1, a2, a3, bq1.z, bq1.w);
            }
        }
    }

    // ---- sumsq: warp reduce + add ST combo part, single writer ------------
#pragma unroll
    for (int s = 16; s >= 1; s >>= 1) {
#pragma unroll
        for (int j = 0; j < 4; j++)
            ss[j] += __shfl_xor_sync(0xffffffffu, ss[j], s);
    }
    if (lane == 0) {
#pragma unroll
        for (int j = 0; j < 4; j++) {
            int p = warp + 8 * j;
            sumsq_s[p] = ss[j] + g_SSst[key_s[p]];
        }
    }

    // ---- cross-k acc reduction (serialized by kq; both nh in parallel) ----
    {
        int row = lane >> 2;
        int cb  = nh * 32 + (lane & 3) * 2;
        if (kq == 3) {
#pragma unroll
            for (int mt = 0; mt < 2; mt++)
#pragma unroll
            for (int nt = 0; nt < 4; nt++) {
                int col = cb + nt * 8;
                int r0 = mt * 16 + row;
                Rbuf[r0 * RS + col]           = acc[mt][nt][0];
                Rbuf[r0 * RS + col + 1]       = acc[mt][nt][1];
                Rbuf[(r0 + 8) * RS + col]     = acc[mt][nt][2];
                Rbuf[(r0 + 8) * RS + col + 1] = acc[mt][nt][3];
            }
        }
        __syncthreads();
        if (kq == 2) {
#pragma unroll
            for (int mt = 0; mt < 2; mt++)
#pragma unroll
            for (int nt = 0; nt < 4; nt++) {
                int col = cb + nt * 8;
                int r0 = mt * 16 + row;
                Rbuf[r0 * RS + col]           += acc[mt][nt][0];
                Rbuf[r0 * RS + col + 1]       += acc[mt][nt][1];
                Rbuf[(r0 + 8) * RS + col]     += acc[mt][nt][2];
                Rbuf[(r0 + 8) * RS + col + 1] += acc[mt][nt][3];
            }
        }
        __syncthreads();
        if (kq == 1) {
#pragma unroll
            for (int mt = 0; mt < 2; mt++)
#pragma unroll
            for (int nt = 0; nt < 4; nt++) {
                int col = cb + nt * 8;
                int r0 = mt * 16 + row;
                Rbuf[r0 * RS + col]           += acc[mt][nt][0];
                Rbuf[r0 * RS + col + 1]       += acc[mt][nt][1];
                Rbuf[(r0 + 8) * RS + col]     += acc[mt][nt][2];
                Rbuf[(r0 + 8) * RS + col + 1] += acc[mt][nt][3];
            }
        }
        __syncthreads();
        if (kq == 0) {
#pragma unroll
            for (int mt = 0; mt < 2; mt++) {
                int r0 = mt * 16 + row;
                int r1 = r0 + 8;
                const float* H0 = g_Hst + key_s[r0] * 64;
                const float* H1 = g_Hst + key_s[r1] * 64;
                float inv0 = 1.0f / (sqrtf(sumsq_s[r0] * (1.0f / 12240.0f)) + 1e-8f);
                float inv1 = 1.0f / (sqrtf(sumsq_s[r1] * (1.0f / 12240.0f)) + 1e-8f);
#pragma unroll
                for (int nt = 0; nt < 4; nt++) {
                    int col = cb + nt * 8;
                    Rbuf[r0 * RS + col]     = fmaxf((acc[mt][nt][0] + Rbuf[r0 * RS + col]     + H0[col])     * inv0, 0.f);
                    Rbuf[r0 * RS + col + 1] = fmaxf((acc[mt][nt][1] + Rbuf[r0 * RS + col + 1] + H0[col + 1]) * inv0, 0.f);
                    Rbuf[r1 * RS + col]     = fmaxf((acc[mt][nt][2] + Rbuf[r1 * RS + col]     + H1[col])     * inv1, 0.f);
                    Rbuf[r1 * RS + col + 1] = fmaxf((acc[mt][nt][3] + Rbuf[r1 * RS + col + 1] + H1[col + 1]) * inv1, 0.f);
                }
            }
        }
    }
    __syncthreads();

    // ---- final tiny layer + sigmoid ---------------------------------------
    if (tid < MPTS) {
        int gp = p0 + tid;
        float o0 = b_final[0], o1 = b_final[1], o2 = b_final[2], o3 = b_final[3];
#pragma unroll 8
        for (int i = 0; i < 64; i++) {
            float h = Rbuf[tid * RS + i];
            float4 wf = *reinterpret_cast<const float4*>(w_final + i * 4);
            o0 += h * wf.x; o1 += h * wf.y; o2 += h * wf.z; o3 += h * wf.w;
        }
#pragma unroll
        for (int c = 0; c < 3; c++) {
            float dv = d_dir[gp * 3 + c];
            float4 wf = *reinterpret_cast<const float4*>(w_final + (64 + c) * 4);
            o0 += dv * wf.x; o1 += dv * wf.y; o2 += dv * wf.z; o3 += dv * wf.w;
        }
        {
            float tv = d_t[gp];
            float4 wf = *reinterpret_cast<const float4*>(w_final + 67 * 4);
            o0 += tv * wf.x; o1 += tv * wf.y; o2 += tv * wf.z; o3 += tv * wf.w;
        }
        d_out[gp * 4 + 0] = 1.0f / (1.0f + expf(-o0));
        d_out[gp * 4 + 1] = 1.0f / (1.0f + expf(-o1));
        d_out[gp * 4 + 2] = 1.0f / (1.0f + expf(-o2));
        d_out[gp * 4 + 3] = 1.0f / (1.0f + expf(-o3));
    }
}

extern "C" void kernel_launch(void* const* d_in, const int* in_sizes, int n_in,
                              void* d_out, int out_size) {
    const float* pos       = (const float*)d_in[0];
    const float* dirv      = (const float*)d_in[1];
    const float* t         = (const float*)d_in[2];
    const float* table0    = (const float*)d_in[3];
    const float* table1    = (const float*)d_in[4];
    const float* table2    = (const float*)d_in[5];
    const float* table3    = (const float*)d_in[6];
    const float* st1       = (const float*)d_in[7];
    const float* st2       = (const float*)d_in[8];
    const float* tf3       = (const float*)d_in[9];
    const float* rms_scale = (const float*)d_in[10];
    const float* w_down    = (const float*)d_in[11];
    const float* w_final   = (const float*)d_in[12];
    const float* b_final   = (const float*)d_in[13];
    float* out = (float*)d_out;

    wf_precompute_kernel<<<(WF4_N + WST_N + NCOMBO + 255) / 256, 256>>>(w_down, rms_scale);
    mark_live_kernel<<<(NPTS + 255) / 256, 256>>>(t);
    st_precompute_kernel<<<NCOMBO, 256>>>(st1, st2, tf3);
    stlt_fused_kernel<<<8192 / MPTS, TPB>>>(
        pos, dirv, t, table0, table1, table2, table3,
        w_final, b_final, out);
}